// round 11
// baseline (speedup 1.0000x reference)
#include <cuda_runtime.h>
#include <cuda_fp16.h>
#include <cstdint>

// ----------------------------------------------------------------------------
// Problem constants
// ----------------------------------------------------------------------------
#define BATCH 4
#define SEQ   2048
#define DMODEL 1024
#define NHEAD 16
#define HDIM  64
#define N_QKV 3072
#define QK_SCALE 0.125f

// ----------------------------------------------------------------------------
// Device scratch
// ----------------------------------------------------------------------------
__device__ alignas(128) __half g_Xh[BATCH * SEQ * DMODEL];
__device__ alignas(128) __half g_Wqkvh[N_QKV * DMODEL];
__device__ alignas(128) __half g_Woh[DMODEL * DMODEL];
__device__ alignas(128) __half g_Q[BATCH * NHEAD * SEQ * HDIM];   // pre-scaled by 0.125
__device__ alignas(128) __half g_K[BATCH * NHEAD * SEQ * HDIM];
__device__ alignas(128) __half g_V[BATCH * NHEAD * SEQ * HDIM];
__device__ alignas(128) __half g_Oh[BATCH * SEQ * DMODEL];
__device__ alignas(128) float  g_cos[SEQ * (HDIM / 2)];
__device__ alignas(128) float  g_sin[SEQ * (HDIM / 2)];

// ----------------------------------------------------------------------------
// Helpers
// ----------------------------------------------------------------------------
__device__ __forceinline__ void mma_f16(float* c,
                                        uint32_t a0, uint32_t a1, uint32_t a2, uint32_t a3,
                                        uint32_t b0, uint32_t b1) {
    asm volatile(
        "mma.sync.aligned.m16n8k16.row.col.f32.f16.f16.f32 "
        "{%0,%1,%2,%3},{%4,%5,%6,%7},{%8,%9},{%0,%1,%2,%3};"
        : "+f"(c[0]), "+f"(c[1]), "+f"(c[2]), "+f"(c[3])
        : "r"(a0), "r"(a1), "r"(a2), "r"(a3), "r"(b0), "r"(b1));
}

__device__ __forceinline__ void cp_async16(void* s, const void* g) {
    uint32_t sa = (uint32_t)__cvta_generic_to_shared(s);
    asm volatile("cp.async.cg.shared.global [%0],[%1],16;" :: "r"(sa), "l"(g));
}
#define CP_COMMIT() asm volatile("cp.async.commit_group;")
#define CP_WAIT0()  asm volatile("cp.async.wait_group 0;")
#define CP_WAIT1()  asm volatile("cp.async.wait_group 1;")

__device__ __forceinline__ uint32_t packh2(float a, float b) {
    __half2 h = __float22half2_rn(make_float2(a, b));
    return *(uint32_t*)&h;
}

__device__ __forceinline__ uint32_t smem_u32(const void* p) {
    return (uint32_t)__cvta_generic_to_shared(p);
}

__device__ __forceinline__ void ldsm_x4(uint32_t& r0, uint32_t& r1,
                                        uint32_t& r2, uint32_t& r3, uint32_t addr) {
    asm volatile("ldmatrix.sync.aligned.m8n8.x4.shared.b16 {%0,%1,%2,%3},[%4];"
                 : "=r"(r0), "=r"(r1), "=r"(r2), "=r"(r3) : "r"(addr));
}

__device__ __forceinline__ void ldsm_x4_t(uint32_t& r0, uint32_t& r1,
                                          uint32_t& r2, uint32_t& r3, uint32_t addr) {
    asm volatile("ldmatrix.sync.aligned.m8n8.x4.trans.shared.b16 {%0,%1,%2,%3},[%4];"
                 : "=r"(r0), "=r"(r1), "=r"(r2), "=r"(r3) : "r"(addr));
}

// ----------------------------------------------------------------------------
// Prepass: fp32 -> fp16, all three tensors in ONE launch
// ----------------------------------------------------------------------------
#define X8 (BATCH * SEQ * DMODEL / 8)
#define W8 (N_QKV * DMODEL / 8)
#define O8 (DMODEL * DMODEL / 8)

__global__ void cvt_all_kernel(const float* __restrict__ x,
                               const float* __restrict__ wqkv,
                               const float* __restrict__ wo) {
    int i = blockIdx.x * blockDim.x + threadIdx.x;
    const float* src;
    __half* dst;
    int j;
    if (i < X8)            { src = x;    dst = g_Xh;    j = i; }
    else if (i < X8 + W8)  { src = wqkv; dst = g_Wqkvh; j = i - X8; }
    else                   { src = wo;   dst = g_Woh;   j = i - X8 - W8; }
    float4 v0 = ((const float4*)src)[2 * j];
    float4 v1 = ((const float4*)src)[2 * j + 1];
    uint32_t p[4];
    p[0] = packh2(v0.x, v0.y);
    p[1] = packh2(v0.z, v0.w);
    p[2] = packh2(v1.x, v1.y);
    p[3] = packh2(v1.z, v1.w);
    ((uint4*)dst)[j] = *(uint4*)p;
}

// ----------------------------------------------------------------------------
// RoPE cos/sin table
// ----------------------------------------------------------------------------
__global__ void rope_table_kernel() {
    int idx = blockIdx.x * blockDim.x + threadIdx.x;
    int pos = idx >> 5;
    int i   = idx & 31;
    float inv_freq = powf(10000.0f, (-2.0f * (float)i) / 64.0f);
    float ang = (float)pos * inv_freq;
    float s, c;
    sincosf(ang, &s, &c);
    g_cos[idx] = c;
    g_sin[idx] = s;
}

// ----------------------------------------------------------------------------
// fp16 GEMM via mma.sync + ldmatrix (unchanged from round 8)
// ----------------------------------------------------------------------------
#define GBM 128
#define GBN 128
#define GBK 64
#define GSTR 72
#define ASTAGE (GBM * GSTR * 2)
#define GEMM_SMEM_H (4 * ASTAGE)

template <int EPI>
__global__ __launch_bounds__(256) void gemm_h(float* __restrict__ Cout) {
    extern __shared__ char smraw[];
    char* Asm = smraw;
    char* Bsm = smraw + 2 * ASTAGE;

    const __half* A = EPI ? (const __half*)g_Xh : (const __half*)g_Oh;
    const __half* W = EPI ? (const __half*)g_Wqkvh : (const __half*)g_Woh;
    const int Kd = DMODEL;

    int tid = threadIdx.x;
    int warp = tid >> 5, lane = tid & 31;
    int g = lane >> 2, t = lane & 3;
    int wm = warp >> 2, wn = warp & 3;
    int bm = blockIdx.y * GBM, bn = blockIdx.x * GBN;

    int a_m = (lane & 7) | (lane & 8);
    int a_k = (lane & 16) >> 1;
    int b_n = (lane & 7) | ((lane & 16) >> 1);
    int b_k = lane & 8;

    uint32_t smbA = smem_u32(Asm);
    uint32_t smbB = smem_u32(Bsm);

    float acc[4][4][4];
#pragma unroll
    for (int i = 0; i < 4; i++)
#pragma unroll
        for (int j = 0; j < 4; j++)
#pragma unroll
            for (int q = 0; q < 4; q++) acc[i][j][q] = 0.0f;

#pragma unroll
    for (int s = 0; s < 2; s++) {
        int k0 = s * GBK;
#pragma unroll
        for (int i = 0; i < 8; i++) {
            int f = tid + i * 256;
            if (f < 1024) {
                int r = f >> 3, cc = f & 7;
                cp_async16(Asm + ((s * GBM + r) * GSTR + cc * 8) * 2,
                           &A[(size_t)(bm + r) * Kd + k0 + cc * 8]);
            } else {
                int fb = f - 1024;
                int r = fb >> 3, cc = fb & 7;
                cp_async16(Bsm + ((s * GBN + r) * GSTR + cc * 8) * 2,
                           &W[(size_t)(bn + r) * Kd + k0 + cc * 8]);
            }
        }
        CP_COMMIT();
    }

    const int NIT = Kd / GBK;   // 16
    for (int it = 0; it < NIT; it++) {
        if (it + 2 < NIT) { CP_WAIT1(); } else { CP_WAIT0(); }
        __syncthreads();
        int buf = it & 1;
        uint32_t aB = smbA + buf * ASTAGE;
        uint32_t bB = smbB + buf * ASTAGE;
#pragma unroll
        for (int ks = 0; ks < 4; ks++) {
            uint32_t af[4][4], bf[4][2];
#pragma unroll
            for (int mt = 0; mt < 4; mt++) {
                uint32_t addr = aB + (((wm * 64 + mt * 16 + a_m) * GSTR + ks * 16 + a_k) * 2);
                ldsm_x4(af[mt][0], af[mt][1], af[mt][2], af[mt][3], addr);
            }
#pragma unroll
            for (int p = 0; p < 2; p++) {
                uint32_t addr = bB + (((wn * 32 + p * 16 + b_n) * GSTR + ks * 16 + b_k) * 2);
                uint32_t r0, r1, r2, r3;
                ldsm_x4(r0, r1, r2, r3, addr);
                bf[2 * p][0] = r0;     bf[2 * p][1] = r1;
                bf[2 * p + 1][0] = r2; bf[2 * p + 1][1] = r3;
            }
#pragma unroll
            for (int mt = 0; mt < 4; mt++)
#pragma unroll
                for (int nt = 0; nt < 4; nt++)
                    mma_f16(acc[mt][nt], af[mt][0], af[mt][1], af[mt][2], af[mt][3],
                            bf[nt][0], bf[nt][1]);
        }
        __syncthreads();
        if (it + 2 < NIT) {
            int k0 = (it + 2) * GBK;
#pragma unroll
            for (int i = 0; i < 8; i++) {
                int f = tid + i * 256;
                if (f < 1024) {
                    int r = f >> 3, cc = f & 7;
                    cp_async16(Asm + ((buf * GBM + r) * GSTR + cc * 8) * 2,
                               &A[(size_t)(bm + r) * Kd + k0 + cc * 8]);
                } else {
                    int fb = f - 1024;
                    int r = fb >> 3, cc = fb & 7;
                    cp_async16(Bsm + ((buf * GBN + r) * GSTR + cc * 8) * 2,
                               &W[(size_t)(bn + r) * Kd + k0 + cc * 8]);
                }
            }
            CP_COMMIT();
        }
    }

    if (EPI == 0) {
#pragma unroll
        for (int mt = 0; mt < 4; mt++) {
#pragma unroll
            for (int nt = 0; nt < 4; nt++) {
                int n = bn + wn * 32 + nt * 8 + 2 * t;
                int r = bm + wm * 64 + mt * 16 + g;
                *(float2*)&Cout[(size_t)r * DMODEL + n] =
                    make_float2(acc[mt][nt][0], acc[mt][nt][1]);
                *(float2*)&Cout[(size_t)(r + 8) * DMODEL + n] =
                    make_float2(acc[mt][nt][2], acc[mt][nt][3]);
            }
        }
    } else {
        int sect = bn >> 10;
        __half* dst = (sect == 0) ? g_Q : ((sect == 1) ? g_K : g_V);
#pragma unroll
        for (int mt = 0; mt < 4; mt++) {
#pragma unroll
            for (int nt = 0; nt < 4; nt++) {
                int n = bn + wn * 32 + nt * 8 + 2 * t;
                int hh = (n & 1023) >> 6;
                int d = n & 63;
                int fi = d >> 1;
                int r0 = bm + wm * 64 + mt * 16 + g;
#pragma unroll
                for (int half_i = 0; half_i < 2; half_i++) {
                    int rr = r0 + half_i * 8;
                    float v0 = acc[mt][nt][half_i * 2 + 0];
                    float v1 = acc[mt][nt][half_i * 2 + 1];
                    int bb = rr >> 11, s = rr & (SEQ - 1);
                    size_t base = ((size_t)((bb * NHEAD + hh) * SEQ + s)) * HDIM + d;
                    float o0, o1;
                    if (sect == 2) { o0 = v0; o1 = v1; }
                    else {
                        float cs = g_cos[s * 32 + fi], sn = g_sin[s * 32 + fi];
                        o0 = v0 * cs - v1 * sn;
                        o1 = v0 * sn + v1 * cs;
                        if (sect == 0) { o0 *= QK_SCALE; o1 *= QK_SCALE; }
                    }
                    *(uint32_t*)&dst[base] = packh2(o0, o1);
                }
            }
        }
    }
}

// ----------------------------------------------------------------------------
// Flash attention. Round-9 changes:
//  - uniform diagonal/interior tile split: causal compare/select ALU only on
//    the single diagonal tile (kti == ntile-1); interior tiles apply just the
//    padding mask as an additive bias.
//  - exp guards removed: masked scores are -1e30 -> __expf underflows to 0.
// ----------------------------------------------------------------------------
#define FSTR 72
#define NEG_BIG (-1e30f)

__global__ __launch_bounds__(128) void flash_h(const int* __restrict__ pm) {
    __shared__ alignas(16) __half Qs[64][FSTR];
    __shared__ alignas(16) __half Ks[2][64][FSTR];
    __shared__ alignas(16) __half Vs[2][64][FSTR];
    __shared__ int pmS[2][64];

    int tid = threadIdx.x;
    int w = tid >> 5, lane = tid & 31;
    int g = lane >> 2, t = lane & 3;
    int bh = blockIdx.y, b = bh >> 4, h = bh & 15;
    int qb = blockIdx.x * 64;

    const __half* Qg = g_Q + (size_t)bh * SEQ * HDIM;
    const __half* Kg = g_K + (size_t)bh * SEQ * HDIM;
    const __half* Vg = g_V + (size_t)bh * SEQ * HDIM;

    int ntile = (qb >> 6) + 1;

    {
#pragma unroll
        for (int i = 0; i < 4; i++) {
            int f = tid + i * 128;
            int r = f >> 3, c = (f & 7) << 3;
            cp_async16(&Qs[r][c], &Qg[(size_t)(qb + r) * HDIM + c]);
            cp_async16(&Ks[0][r][c], &Kg[(size_t)r * HDIM + c]);
            cp_async16(&Vs[0][r][c], &Vg[(size_t)r * HDIM + c]);
        }
        if (tid < 16) cp_async16(&pmS[0][tid * 4], &pm[b * SEQ + tid * 4]);
        CP_COMMIT();
    }

    float m0 = -1e30f, m1 = -1e30f, l0 = 0.0f, l1 = 0.0f;
    float acc[8][4];
#pragma unroll
    for (int i = 0; i < 8; i++)
#pragma unroll
        for (int j = 0; j < 4; j++) acc[i][j] = 0.0f;

    int r0 = qb + w * 16 + g;
    int r1 = r0 + 8;

    uint32_t qf[4][4];
    int Lr = (lane & 7) | (lane & 8);
    int Lc = (lane & 16) ? 8 : 0;
    int b_n = (lane & 7) | ((lane & 16) >> 1);
    int b_k = lane & 8;
    uint32_t vbase0 = smem_u32(&Vs[0][0][0]);
    uint32_t vbase1 = smem_u32(&Vs[1][0][0]);
    uint32_t kbase0 = smem_u32(&Ks[0][0][0]);
    uint32_t kbase1 = smem_u32(&Ks[1][0][0]);

    for (int kti = 0; kti < ntile; kti++) {
        int kt = kti * 64;
        int buf = kti & 1;
        bool diag = (kti == ntile - 1);   // uniform across the block
        if (!diag) {
            int nk0 = (kti + 1) * 64;
#pragma unroll
            for (int i = 0; i < 4; i++) {
                int f = tid + i * 128;
                int r = f >> 3, c = (f & 7) << 3;
                cp_async16(&Ks[buf ^ 1][r][c], &Kg[(size_t)(nk0 + r) * HDIM + c]);
                cp_async16(&Vs[buf ^ 1][r][c], &Vg[(size_t)(nk0 + r) * HDIM + c]);
            }
            if (tid < 16) cp_async16(&pmS[buf ^ 1][tid * 4], &pm[b * SEQ + nk0 + tid * 4]);
            CP_COMMIT();
            CP_WAIT1();
        } else {
            CP_WAIT0();
        }
        __syncthreads();

        if (kti == 0) {
#pragma unroll
            for (int kk = 0; kk < 4; kk++) {
                int c = kk * 16 + 2 * t;
                qf[kk][0] = *(const uint32_t*)&Qs[w * 16 + g][c];
                qf[kk][1] = *(const uint32_t*)&Qs[w * 16 + g + 8][c];
                qf[kk][2] = *(const uint32_t*)&Qs[w * 16 + g][c + 8];
                qf[kk][3] = *(const uint32_t*)&Qs[w * 16 + g + 8][c + 8];
            }
        }

        // ---- S = Q @ K^T (K frags via ldmatrix.x4) ----
        float sf[8][4];
#pragma unroll
        for (int i = 0; i < 8; i++)
#pragma unroll
            for (int j = 0; j < 4; j++) sf[i][j] = 0.0f;

        uint32_t kb = buf ? kbase1 : kbase0;
#pragma unroll
        for (int kk = 0; kk < 4; kk++) {
            uint32_t bfr[8][2];
#pragma unroll
            for (int p = 0; p < 4; p++) {
                uint32_t addr = kb + (((p * 16 + b_n) * FSTR + kk * 16 + b_k) * 2);
                uint32_t r0_, r1_, r2_, r3_;
                ldsm_x4(r0_, r1_, r2_, r3_, addr);
                bfr[2 * p][0] = r0_;     bfr[2 * p][1] = r1_;
                bfr[2 * p + 1][0] = r2_; bfr[2 * p + 1][1] = r3_;
            }
#pragma unroll
            for (int n = 0; n < 8; n++)
                mma_f16(sf[n], qf[kk][0], qf[kk][1], qf[kk][2], qf[kk][3],
                        bfr[n][0], bfr[n][1]);
        }

        // ---- mask + per-thread max ----
        float tmax0 = -1e30f, tmax1 = -1e30f;
        if (diag) {
            // full causal + padding mask (one tile per block)
#pragma unroll
            for (int nk = 0; nk < 8; nk++) {
                int c0 = kt + nk * 8 + 2 * t;
                int c1 = c0 + 1;
                bool k0ok = pmS[buf][nk * 8 + 2 * t] != 0;
                bool k1ok = pmS[buf][nk * 8 + 2 * t + 1] != 0;
                sf[nk][0] = (k0ok && c0 <= r0) ? sf[nk][0] : NEG_BIG;
                sf[nk][1] = (k1ok && c1 <= r0) ? sf[nk][1] : NEG_BIG;
                sf[nk][2] = (k0ok && c0 <= r1) ? sf[nk][2] : NEG_BIG;
                sf[nk][3] = (k1ok && c1 <= r1) ? sf[nk][3] : NEG_BIG;
                tmax0 = fmaxf(tmax0, fmaxf(sf[nk][0], sf[nk][1]));
                tmax1 = fmaxf(tmax1, fmaxf(sf[nk][2], sf[nk][3]));
            }
        } else {
            // interior tile: padding mask only, as additive bias
#pragma unroll
            for (int nk = 0; nk < 8; nk++) {
                float b0 = pmS[buf][nk * 8 + 2 * t] ? 0.0f : NEG_BIG;
                float b1 = pmS[buf][nk * 8 + 2 * t + 1] ? 0.0f : NEG_BIG;
                sf[nk][0] += b0; sf[nk][1] += b1;
                sf[nk][2] += b0; sf[nk][3] += b1;
                tmax0 = fmaxf(tmax0, fmaxf(sf[nk][0], sf[nk][1]));
                tmax1 = fmaxf(tmax1, fmaxf(sf[nk][2], sf[nk][3]));
            }
        }
        tmax0 = fmaxf(tmax0, __shfl_xor_sync(0xFFFFFFFFu, tmax0, 1));
        tmax0 = fmaxf(tmax0, __shfl_xor_sync(0xFFFFFFFFu, tmax0, 2));
        tmax1 = fmaxf(tmax1, __shfl_xor_sync(0xFFFFFFFFu, tmax1, 1));
        tmax1 = fmaxf(tmax1, __shfl_xor_sync(0xFFFFFFFFu, tmax1, 2));

        float mn0 = fmaxf(m0, tmax0), mn1 = fmaxf(m1, tmax1);
        float al0 = __expf(m0 - mn0), al1 = __expf(m1 - mn1);
        m0 = mn0; m1 = mn1;

        // exp (unguarded: masked -1e30 scores underflow to exactly 0)
        uint32_t pf[4][4];
        float ps0 = 0.0f, ps1 = 0.0f;
#pragma unroll
        for (int nk = 0; nk < 8; nk++) {
            float p00 = __expf(sf[nk][0] - mn0);
            float p01 = __expf(sf[nk][1] - mn0);
            float p10 = __expf(sf[nk][2] - mn1);
            float p11 = __expf(sf[nk][3] - mn1);
            ps0 += p00 + p01;
            ps1 += p10 + p11;
            int kk = nk >> 1;
            if ((nk & 1) == 0) { pf[kk][0] = packh2(p00, p01); pf[kk][1] = packh2(p10, p11); }
            else               { pf[kk][2] = packh2(p00, p01); pf[kk][3] = packh2(p10, p11); }
        }
        ps0 += __shfl_xor_sync(0xFFFFFFFFu, ps0, 1);
        ps0 += __shfl_xor_sync(0xFFFFFFFFu, ps0, 2);
        ps1 += __shfl_xor_sync(0xFFFFFFFFu, ps1, 1);
        ps1 += __shfl_xor_sync(0xFFFFFFFFu, ps1, 2);
        l0 = l0 * al0 + ps0;
        l1 = l1 * al1 + ps1;
#pragma unroll
        for (int nd = 0; nd < 8; nd++) {
            acc[nd][0] *= al0; acc[nd][1] *= al0;
            acc[nd][2] *= al1; acc[nd][3] *= al1;
        }

        // ---- acc += P @ V (V^T frags via ldmatrix.trans) ----
        uint32_t vb = buf ? vbase1 : vbase0;
#pragma unroll
        for (int kk = 0; kk < 4; kk++) {
#pragma unroll
            for (int ndp = 0; ndp < 4; ndp++) {
                uint32_t addr = vb + (uint32_t)(((kk * 16 + Lr) * FSTR + ndp * 16 + Lc) * 2);
                uint32_t v0, v1, v2, v3;
                ldsm_x4_t(v0, v1, v2, v3, addr);
                mma_f16(acc[2 * ndp],     pf[kk][0], pf[kk][1], pf[kk][2], pf[kk][3], v0, v1);
                mma_f16(acc[2 * ndp + 1], pf[kk][0], pf[kk][1], pf[kk][2], pf[kk][3], v2, v3);
            }
        }
        __syncthreads();
    }

    float inv0 = 1.0f / l0, inv1 = 1.0f / l1;
    size_t base0 = ((size_t)(b * SEQ + r0)) * DMODEL + h * HDIM;
    size_t base1 = ((size_t)(b * SEQ + r1)) * DMODEL + h * HDIM;
#pragma unroll
    for (int nd = 0; nd < 8; nd++) {
        int c = nd * 8 + 2 * t;
        *(uint32_t*)&g_Oh[base0 + c] = packh2(acc[nd][0] * inv0, acc[nd][1] * inv0);
        *(uint32_t*)&g_Oh[base1 + c] = packh2(acc[nd][2] * inv1, acc[nd][3] * inv1);
    }
}

// ----------------------------------------------------------------------------
// Launch
// ----------------------------------------------------------------------------
extern "C" void kernel_launch(void* const* d_in, const int* in_sizes, int n_in,
                              void* d_out, int out_size) {
    const float* x     = (const float*)d_in[0];
    const int*   pmask = (const int*)d_in[1];
    const float* w_qkv = (const float*)d_in[2];
    const float* w_o   = (const float*)d_in[3];
    float* out = (float*)d_out;

    cudaFuncSetAttribute(gemm_h<1>, cudaFuncAttributeMaxDynamicSharedMemorySize, GEMM_SMEM_H);
    cudaFuncSetAttribute(gemm_h<0>, cudaFuncAttributeMaxDynamicSharedMemorySize, GEMM_SMEM_H);

    cvt_all_kernel<<<(X8 + W8 + O8) / 256, 256>>>(x, w_qkv, w_o);
    rope_table_kernel<<<SEQ * 32 / 256, 256>>>();
    gemm_h<1><<<dim3(N_QKV / GBN, (BATCH * SEQ) / GBM), 256, GEMM_SMEM_H>>>(nullptr);
    flash_h<<<dim3(SEQ / 64, BATCH * NHEAD), 128>>>(pmask);
    gemm_h<0><<<dim3(DMODEL / GBN, (BATCH * SEQ) / GBM), 256, GEMM_SMEM_H>>>(out);
}

// round 12
// speedup vs baseline: 1.5095x; 1.5095x over previous
#include <cuda_runtime.h>
#include <cuda_fp16.h>
#include <cstdint>

// ----------------------------------------------------------------------------
// Problem constants
// ----------------------------------------------------------------------------
#define BATCH 4
#define SEQ   2048
#define DMODEL 1024
#define NHEAD 16
#define HDIM  64
#define N_QKV 3072
#define QK_SCALE 0.125f

// ----------------------------------------------------------------------------
// Device scratch
// ----------------------------------------------------------------------------
__device__ alignas(128) __half g_Xh[BATCH * SEQ * DMODEL];
__device__ alignas(128) __half g_Wqkvh[N_QKV * DMODEL];
__device__ alignas(128) __half g_Woh[DMODEL * DMODEL];
__device__ alignas(128) __half g_Q[BATCH * NHEAD * SEQ * HDIM];   // pre-scaled by 0.125
__device__ alignas(128) __half g_K[BATCH * NHEAD * SEQ * HDIM];
__device__ alignas(128) __half g_V[BATCH * NHEAD * SEQ * HDIM];
__device__ alignas(128) __half g_Oh[BATCH * SEQ * DMODEL];
__device__ alignas(128) float  g_cos[SEQ * (HDIM / 2)];
__device__ alignas(128) float  g_sin[SEQ * (HDIM / 2)];

// ----------------------------------------------------------------------------
// Helpers
// ----------------------------------------------------------------------------
__device__ __forceinline__ void mma_f16(float* c,
                                        uint32_t a0, uint32_t a1, uint32_t a2, uint32_t a3,
                                        uint32_t b0, uint32_t b1) {
    asm volatile(
        "mma.sync.aligned.m16n8k16.row.col.f32.f16.f16.f32 "
        "{%0,%1,%2,%3},{%4,%5,%6,%7},{%8,%9},{%0,%1,%2,%3};"
        : "+f"(c[0]), "+f"(c[1]), "+f"(c[2]), "+f"(c[3])
        : "r"(a0), "r"(a1), "r"(a2), "r"(a3), "r"(b0), "r"(b1));
}

__device__ __forceinline__ void cp_async16(void* s, const void* g) {
    uint32_t sa = (uint32_t)__cvta_generic_to_shared(s);
    asm volatile("cp.async.cg.shared.global [%0],[%1],16;" :: "r"(sa), "l"(g));
}
#define CP_COMMIT() asm volatile("cp.async.commit_group;")
#define CP_WAIT0()  asm volatile("cp.async.wait_group 0;")
#define CP_WAIT1()  asm volatile("cp.async.wait_group 1;")

__device__ __forceinline__ uint32_t packh2(float a, float b) {
    __half2 h = __float22half2_rn(make_float2(a, b));
    return *(uint32_t*)&h;
}

__device__ __forceinline__ uint32_t smem_u32(const void* p) {
    return (uint32_t)__cvta_generic_to_shared(p);
}

__device__ __forceinline__ void ldsm_x4(uint32_t& r0, uint32_t& r1,
                                        uint32_t& r2, uint32_t& r3, uint32_t addr) {
    asm volatile("ldmatrix.sync.aligned.m8n8.x4.shared.b16 {%0,%1,%2,%3},[%4];"
                 : "=r"(r0), "=r"(r1), "=r"(r2), "=r"(r3) : "r"(addr));
}

__device__ __forceinline__ void ldsm_x4_t(uint32_t& r0, uint32_t& r1,
                                          uint32_t& r2, uint32_t& r3, uint32_t addr) {
    asm volatile("ldmatrix.sync.aligned.m8n8.x4.trans.shared.b16 {%0,%1,%2,%3},[%4];"
                 : "=r"(r0), "=r"(r1), "=r"(r2), "=r"(r3) : "r"(addr));
}

// ----------------------------------------------------------------------------
// Prepass: fp32 -> fp16, all three tensors in ONE launch
// ----------------------------------------------------------------------------
#define X8 (BATCH * SEQ * DMODEL / 8)
#define W8 (N_QKV * DMODEL / 8)
#define O8 (DMODEL * DMODEL / 8)

__global__ void cvt_all_kernel(const float* __restrict__ x,
                               const float* __restrict__ wqkv,
                               const float* __restrict__ wo) {
    int i = blockIdx.x * blockDim.x + threadIdx.x;
    const float* src;
    __half* dst;
    int j;
    if (i < X8)            { src = x;    dst = g_Xh;    j = i; }
    else if (i < X8 + W8)  { src = wqkv; dst = g_Wqkvh; j = i - X8; }
    else                   { src = wo;   dst = g_Woh;   j = i - X8 - W8; }
    float4 v0 = ((const float4*)src)[2 * j];
    float4 v1 = ((const float4*)src)[2 * j + 1];
    uint32_t p[4];
    p[0] = packh2(v0.x, v0.y);
    p[1] = packh2(v0.z, v0.w);
    p[2] = packh2(v1.x, v1.y);
    p[3] = packh2(v1.z, v1.w);
    ((uint4*)dst)[j] = *(uint4*)p;
}

// ----------------------------------------------------------------------------
// RoPE cos/sin table
// ----------------------------------------------------------------------------
__global__ void rope_table_kernel() {
    int idx = blockIdx.x * blockDim.x + threadIdx.x;
    int pos = idx >> 5;
    int i   = idx & 31;
    float inv_freq = powf(10000.0f, (-2.0f * (float)i) / 64.0f);
    float ang = (float)pos * inv_freq;
    float s, c;
    sincosf(ang, &s, &c);
    g_cos[idx] = c;
    g_sin[idx] = s;
}

// ----------------------------------------------------------------------------
// fp16 GEMM via mma.sync + ldmatrix (round-8 version, unchanged)
// ----------------------------------------------------------------------------
#define GBM 128
#define GBN 128
#define GBK 64
#define GSTR 72
#define ASTAGE (GBM * GSTR * 2)
#define GEMM_SMEM_H (4 * ASTAGE)

template <int EPI>
__global__ __launch_bounds__(256) void gemm_h(float* __restrict__ Cout) {
    extern __shared__ char smraw[];
    char* Asm = smraw;
    char* Bsm = smraw + 2 * ASTAGE;

    const __half* A = EPI ? (const __half*)g_Xh : (const __half*)g_Oh;
    const __half* W = EPI ? (const __half*)g_Wqkvh : (const __half*)g_Woh;
    const int Kd = DMODEL;

    int tid = threadIdx.x;
    int warp = tid >> 5, lane = tid & 31;
    int g = lane >> 2, t = lane & 3;
    int wm = warp >> 2, wn = warp & 3;
    int bm = blockIdx.y * GBM, bn = blockIdx.x * GBN;

    int a_m = (lane & 7) | (lane & 8);
    int a_k = (lane & 16) >> 1;
    int b_n = (lane & 7) | ((lane & 16) >> 1);
    int b_k = lane & 8;

    uint32_t smbA = smem_u32(Asm);
    uint32_t smbB = smem_u32(Bsm);

    float acc[4][4][4];
#pragma unroll
    for (int i = 0; i < 4; i++)
#pragma unroll
        for (int j = 0; j < 4; j++)
#pragma unroll
            for (int q = 0; q < 4; q++) acc[i][j][q] = 0.0f;

#pragma unroll
    for (int s = 0; s < 2; s++) {
        int k0 = s * GBK;
#pragma unroll
        for (int i = 0; i < 8; i++) {
            int f = tid + i * 256;
            if (f < 1024) {
                int r = f >> 3, cc = f & 7;
                cp_async16(Asm + ((s * GBM + r) * GSTR + cc * 8) * 2,
                           &A[(size_t)(bm + r) * Kd + k0 + cc * 8]);
            } else {
                int fb = f - 1024;
                int r = fb >> 3, cc = fb & 7;
                cp_async16(Bsm + ((s * GBN + r) * GSTR + cc * 8) * 2,
                           &W[(size_t)(bn + r) * Kd + k0 + cc * 8]);
            }
        }
        CP_COMMIT();
    }

    const int NIT = Kd / GBK;   // 16
    for (int it = 0; it < NIT; it++) {
        if (it + 2 < NIT) { CP_WAIT1(); } else { CP_WAIT0(); }
        __syncthreads();
        int buf = it & 1;
        uint32_t aB = smbA + buf * ASTAGE;
        uint32_t bB = smbB + buf * ASTAGE;
#pragma unroll
        for (int ks = 0; ks < 4; ks++) {
            uint32_t af[4][4], bf[4][2];
#pragma unroll
            for (int mt = 0; mt < 4; mt++) {
                uint32_t addr = aB + (((wm * 64 + mt * 16 + a_m) * GSTR + ks * 16 + a_k) * 2);
                ldsm_x4(af[mt][0], af[mt][1], af[mt][2], af[mt][3], addr);
            }
#pragma unroll
            for (int p = 0; p < 2; p++) {
                uint32_t addr = bB + (((wn * 32 + p * 16 + b_n) * GSTR + ks * 16 + b_k) * 2);
                uint32_t r0, r1, r2, r3;
                ldsm_x4(r0, r1, r2, r3, addr);
                bf[2 * p][0] = r0;     bf[2 * p][1] = r1;
                bf[2 * p + 1][0] = r2; bf[2 * p + 1][1] = r3;
            }
#pragma unroll
            for (int mt = 0; mt < 4; mt++)
#pragma unroll
                for (int nt = 0; nt < 4; nt++)
                    mma_f16(acc[mt][nt], af[mt][0], af[mt][1], af[mt][2], af[mt][3],
                            bf[nt][0], bf[nt][1]);
        }
        __syncthreads();
        if (it + 2 < NIT) {
            int k0 = (it + 2) * GBK;
#pragma unroll
            for (int i = 0; i < 8; i++) {
                int f = tid + i * 256;
                if (f < 1024) {
                    int r = f >> 3, cc = f & 7;
                    cp_async16(Asm + ((buf * GBM + r) * GSTR + cc * 8) * 2,
                               &A[(size_t)(bm + r) * Kd + k0 + cc * 8]);
                } else {
                    int fb = f - 1024;
                    int r = fb >> 3, cc = fb & 7;
                    cp_async16(Bsm + ((buf * GBN + r) * GSTR + cc * 8) * 2,
                               &W[(size_t)(bn + r) * Kd + k0 + cc * 8]);
                }
            }
            CP_COMMIT();
        }
    }

    if (EPI == 0) {
#pragma unroll
        for (int mt = 0; mt < 4; mt++) {
#pragma unroll
            for (int nt = 0; nt < 4; nt++) {
                int n = bn + wn * 32 + nt * 8 + 2 * t;
                int r = bm + wm * 64 + mt * 16 + g;
                *(float2*)&Cout[(size_t)r * DMODEL + n] =
                    make_float2(acc[mt][nt][0], acc[mt][nt][1]);
                *(float2*)&Cout[(size_t)(r + 8) * DMODEL + n] =
                    make_float2(acc[mt][nt][2], acc[mt][nt][3]);
            }
        }
    } else {
        int sect = bn >> 10;
        __half* dst = (sect == 0) ? g_Q : ((sect == 1) ? g_K : g_V);
#pragma unroll
        for (int mt = 0; mt < 4; mt++) {
#pragma unroll
            for (int nt = 0; nt < 4; nt++) {
                int n = bn + wn * 32 + nt * 8 + 2 * t;
                int hh = (n & 1023) >> 6;
                int d = n & 63;
                int fi = d >> 1;
                int r0 = bm + wm * 64 + mt * 16 + g;
#pragma unroll
                for (int half_i = 0; half_i < 2; half_i++) {
                    int rr = r0 + half_i * 8;
                    float v0 = acc[mt][nt][half_i * 2 + 0];
                    float v1 = acc[mt][nt][half_i * 2 + 1];
                    int bb = rr >> 11, s = rr & (SEQ - 1);
                    size_t base = ((size_t)((bb * NHEAD + hh) * SEQ + s)) * HDIM + d;
                    float o0, o1;
                    if (sect == 2) { o0 = v0; o1 = v1; }
                    else {
                        float cs = g_cos[s * 32 + fi], sn = g_sin[s * 32 + fi];
                        o0 = v0 * cs - v1 * sn;
                        o1 = v0 * sn + v1 * cs;
                        if (sect == 0) { o0 *= QK_SCALE; o1 *= QK_SCALE; }
                    }
                    *(uint32_t*)&dst[base] = packh2(o0, o1);
                }
            }
        }
    }
}

// ----------------------------------------------------------------------------
// Flash attention — round-8 structure (select-based masking every tile, no
// tile-role branch). Round-12 deltas only:
//   (a) heavy-first scheduling: qb reversed so 32-tile blocks launch first
//   (b) unguarded exp (masked -1e30 scores underflow to exact 0)
// ----------------------------------------------------------------------------
#define FSTR 72
#define NEG_BIG (-1e30f)

__global__ __launch_bounds__(128) void flash_h(const int* __restrict__ pm) {
    __shared__ alignas(16) __half Qs[64][FSTR];
    __shared__ alignas(16) __half Ks[2][64][FSTR];
    __shared__ alignas(16) __half Vs[2][64][FSTR];
    __shared__ int pmS[2][64];

    int tid = threadIdx.x;
    int w = tid >> 5, lane = tid & 31;
    int g = lane >> 2, t = lane & 3;
    int bh = blockIdx.y, b = bh >> 4, h = bh & 15;
    int qb = (SEQ / 64 - 1 - blockIdx.x) * 64;   // heavy blocks first

    const __half* Qg = g_Q + (size_t)bh * SEQ * HDIM;
    const __half* Kg = g_K + (size_t)bh * SEQ * HDIM;
    const __half* Vg = g_V + (size_t)bh * SEQ * HDIM;

    int ntile = (qb >> 6) + 1;

    {
#pragma unroll
        for (int i = 0; i < 4; i++) {
            int f = tid + i * 128;
            int r = f >> 3, c = (f & 7) << 3;
            cp_async16(&Qs[r][c], &Qg[(size_t)(qb + r) * HDIM + c]);
            cp_async16(&Ks[0][r][c], &Kg[(size_t)r * HDIM + c]);
            cp_async16(&Vs[0][r][c], &Vg[(size_t)r * HDIM + c]);
        }
        if (tid < 16) cp_async16(&pmS[0][tid * 4], &pm[b * SEQ + tid * 4]);
        CP_COMMIT();
    }

    float m0 = -1e30f, m1 = -1e30f, l0 = 0.0f, l1 = 0.0f;
    float acc[8][4];
#pragma unroll
    for (int i = 0; i < 8; i++)
#pragma unroll
        for (int j = 0; j < 4; j++) acc[i][j] = 0.0f;

    int r0 = qb + w * 16 + g;
    int r1 = r0 + 8;

    uint32_t qf[4][4];
    int Lr = (lane & 7) | (lane & 8);
    int Lc = (lane & 16) ? 8 : 0;
    int b_n = (lane & 7) | ((lane & 16) >> 1);
    int b_k = lane & 8;
    uint32_t vbase0 = smem_u32(&Vs[0][0][0]);
    uint32_t vbase1 = smem_u32(&Vs[1][0][0]);
    uint32_t kbase0 = smem_u32(&Ks[0][0][0]);
    uint32_t kbase1 = smem_u32(&Ks[1][0][0]);

    for (int kti = 0; kti < ntile; kti++) {
        int kt = kti * 64;
        int buf = kti & 1;
        if (kti + 1 < ntile) {
            int nk0 = (kti + 1) * 64;
#pragma unroll
            for (int i = 0; i < 4; i++) {
                int f = tid + i * 128;
                int r = f >> 3, c = (f & 7) << 3;
                cp_async16(&Ks[buf ^ 1][r][c], &Kg[(size_t)(nk0 + r) * HDIM + c]);
                cp_async16(&Vs[buf ^ 1][r][c], &Vg[(size_t)(nk0 + r) * HDIM + c]);
            }
            if (tid < 16) cp_async16(&pmS[buf ^ 1][tid * 4], &pm[b * SEQ + nk0 + tid * 4]);
            CP_COMMIT();
            CP_WAIT1();
        } else {
            CP_WAIT0();
        }
        __syncthreads();

        if (kti == 0) {
#pragma unroll
            for (int kk = 0; kk < 4; kk++) {
                int c = kk * 16 + 2 * t;
                qf[kk][0] = *(const uint32_t*)&Qs[w * 16 + g][c];
                qf[kk][1] = *(const uint32_t*)&Qs[w * 16 + g + 8][c];
                qf[kk][2] = *(const uint32_t*)&Qs[w * 16 + g][c + 8];
                qf[kk][3] = *(const uint32_t*)&Qs[w * 16 + g + 8][c + 8];
            }
        }

        // ---- S = Q @ K^T (K frags via ldmatrix.x4) ----
        float sf[8][4];
#pragma unroll
        for (int i = 0; i < 8; i++)
#pragma unroll
            for (int j = 0; j < 4; j++) sf[i][j] = 0.0f;

        uint32_t kb = buf ? kbase1 : kbase0;
#pragma unroll
        for (int kk = 0; kk < 4; kk++) {
            uint32_t bfr[8][2];
#pragma unroll
            for (int p = 0; p < 4; p++) {
                uint32_t addr = kb + (((p * 16 + b_n) * FSTR + kk * 16 + b_k) * 2);
                uint32_t r0_, r1_, r2_, r3_;
                ldsm_x4(r0_, r1_, r2_, r3_, addr);
                bfr[2 * p][0] = r0_;     bfr[2 * p][1] = r1_;
                bfr[2 * p + 1][0] = r2_; bfr[2 * p + 1][1] = r3_;
            }
#pragma unroll
            for (int n = 0; n < 8; n++)
                mma_f16(sf[n], qf[kk][0], qf[kk][1], qf[kk][2], qf[kk][3],
                        bfr[n][0], bfr[n][1]);
        }

        // ---- mask + online softmax (round-8 structure) ----
        float tmax0 = -1e30f, tmax1 = -1e30f;
#pragma unroll
        for (int nk = 0; nk < 8; nk++) {
            int c0 = kt + nk * 8 + 2 * t;
            int c1 = c0 + 1;
            bool k0ok = pmS[buf][nk * 8 + 2 * t] != 0;
            bool k1ok = pmS[buf][nk * 8 + 2 * t + 1] != 0;
            sf[nk][0] = (k0ok && c0 <= r0) ? sf[nk][0] : NEG_BIG;
            sf[nk][1] = (k1ok && c1 <= r0) ? sf[nk][1] : NEG_BIG;
            sf[nk][2] = (k0ok && c0 <= r1) ? sf[nk][2] : NEG_BIG;
            sf[nk][3] = (k1ok && c1 <= r1) ? sf[nk][3] : NEG_BIG;
            tmax0 = fmaxf(tmax0, fmaxf(sf[nk][0], sf[nk][1]));
            tmax1 = fmaxf(tmax1, fmaxf(sf[nk][2], sf[nk][3]));
        }
        tmax0 = fmaxf(tmax0, __shfl_xor_sync(0xFFFFFFFFu, tmax0, 1));
        tmax0 = fmaxf(tmax0, __shfl_xor_sync(0xFFFFFFFFu, tmax0, 2));
        tmax1 = fmaxf(tmax1, __shfl_xor_sync(0xFFFFFFFFu, tmax1, 1));
        tmax1 = fmaxf(tmax1, __shfl_xor_sync(0xFFFFFFFFu, tmax1, 2));

        float mn0 = fmaxf(m0, tmax0), mn1 = fmaxf(m1, tmax1);
        float al0 = __expf(m0 - mn0), al1 = __expf(m1 - mn1);
        m0 = mn0; m1 = mn1;

        // exp (unguarded: masked -1e30 scores underflow to exactly 0)
        uint32_t pf[4][4];
        float ps0 = 0.0f, ps1 = 0.0f;
#pragma unroll
        for (int nk = 0; nk < 8; nk++) {
            float p00 = __expf(sf[nk][0] - mn0);
            float p01 = __expf(sf[nk][1] - mn0);
            float p10 = __expf(sf[nk][2] - mn1);
            float p11 = __expf(sf[nk][3] - mn1);
            ps0 += p00 + p01;
            ps1 += p10 + p11;
            int kk = nk >> 1;
            if ((nk & 1) == 0) { pf[kk][0] = packh2(p00, p01); pf[kk][1] = packh2(p10, p11); }
            else               { pf[kk][2] = packh2(p00, p01); pf[kk][3] = packh2(p10, p11); }
        }
        ps0 += __shfl_xor_sync(0xFFFFFFFFu, ps0, 1);
        ps0 += __shfl_xor_sync(0xFFFFFFFFu, ps0, 2);
        ps1 += __shfl_xor_sync(0xFFFFFFFFu, ps1, 1);
        ps1 += __shfl_xor_sync(0xFFFFFFFFu, ps1, 2);
        l0 = l0 * al0 + ps0;
        l1 = l1 * al1 + ps1;
#pragma unroll
        for (int nd = 0; nd < 8; nd++) {
            acc[nd][0] *= al0; acc[nd][1] *= al0;
            acc[nd][2] *= al1; acc[nd][3] *= al1;
        }

        // ---- acc += P @ V (V^T frags via ldmatrix.trans) ----
        uint32_t vb = buf ? vbase1 : vbase0;
#pragma unroll
        for (int kk = 0; kk < 4; kk++) {
#pragma unroll
            for (int ndp = 0; ndp < 4; ndp++) {
                uint32_t addr = vb + (uint32_t)(((kk * 16 + Lr) * FSTR + ndp * 16 + Lc) * 2);
                uint32_t v0, v1, v2, v3;
                ldsm_x4_t(v0, v1, v2, v3, addr);
                mma_f16(acc[2 * ndp],     pf[kk][0], pf[kk][1], pf[kk][2], pf[kk][3], v0, v1);
                mma_f16(acc[2 * ndp + 1], pf[kk][0], pf[kk][1], pf[kk][2], pf[kk][3], v2, v3);
            }
        }
        __syncthreads();
    }

    float inv0 = 1.0f / l0, inv1 = 1.0f / l1;
    size_t base0 = ((size_t)(b * SEQ + r0)) * DMODEL + h * HDIM;
    size_t base1 = ((size_t)(b * SEQ + r1)) * DMODEL + h * HDIM;
#pragma unroll
    for (int nd = 0; nd < 8; nd++) {
        int c = nd * 8 + 2 * t;
        *(uint32_t*)&g_Oh[base0 + c] = packh2(acc[nd][0] * inv0, acc[nd][1] * inv0);
        *(uint32_t*)&g_Oh[base1 + c] = packh2(acc[nd][2] * inv1, acc[nd][3] * inv1);
    }
}

// ----------------------------------------------------------------------------
// Launch
// ----------------------------------------------------------------------------
extern "C" void kernel_launch(void* const* d_in, const int* in_sizes, int n_in,
                              void* d_out, int out_size) {
    const float* x     = (const float*)d_in[0];
    const int*   pmask = (const int*)d_in[1];
    const float* w_qkv = (const float*)d_in[2];
    const float* w_o   = (const float*)d_in[3];
    float* out = (float*)d_out;

    cudaFuncSetAttribute(gemm_h<1>, cudaFuncAttributeMaxDynamicSharedMemorySize, GEMM_SMEM_H);
    cudaFuncSetAttribute(gemm_h<0>, cudaFuncAttributeMaxDynamicSharedMemorySize, GEMM_SMEM_H);

    cvt_all_kernel<<<(X8 + W8 + O8) / 256, 256>>>(x, w_qkv, w_o);
    rope_table_kernel<<<SEQ * 32 / 256, 256>>>();
    gemm_h<1><<<dim3(N_QKV / GBN, (BATCH * SEQ) / GBM), 256, GEMM_SMEM_H>>>(nullptr);
    flash_h<<<dim3(SEQ / 64, BATCH * NHEAD), 128>>>(pmask);
    gemm_h<0><<<dim3(DMODEL / GBN, (BATCH * SEQ) / GBM), 256, GEMM_SMEM_H>>>(out);
}